// round 8
// baseline (speedup 1.0000x reference)
#include <cuda_runtime.h>
#include <cstdint>

// Focal CTC loss — barrier-free 4-warp pipeline, log2-domain alpha.
// Scan CTA = 1 sample: warp k owns pairs j=32k+lane (states u=2j, v=2j+1).
// alpha flows upward in s only -> warp k consumes warp k-1's lane31 aV via a
// 64-slot smem ring with batched fenced counters (no __syncthreads in the
// scan). Intra-warp neighbor = shfl_up. Emissions LDG'd per lane, PF=8
// register prefetch (800+ cyc cover; L2 pre-warmed by the reduce CTAs).
// CTAs [B,2B): coalesced sum_t exp(lp) -> focal weights. Final scalar
// factorizes: mean(outer(w,loss)) = mean(loss)*mean(w).

#define CFIX  256
#define PF    8
#define RING  64
#define NEG2  (-1e30f)
#define LOG2E 1.4426950408889634f
#define LN2   0.6931471805599453f

__device__ float g_loss[1024];
__device__ float g_wsum[1024];
__device__ unsigned int g_ctr = 0;

__device__ __forceinline__ float ex2f(float x){ float y; asm("ex2.approx.ftz.f32 %0,%1;":"=f"(y):"f"(x)); return y; }
__device__ __forceinline__ float lg2f(float x){ float y; asm("lg2.approx.ftz.f32 %0,%1;":"=f"(y):"f"(x)); return y; }

__device__ __forceinline__ void finalize(float* out, int B, int L, int nCTA)
{
    __threadfence();
    unsigned v = atomicAdd(&g_ctr, 1u);
    if (v == (unsigned)(nCTA - 1)) {
        g_ctr = 0;
        __threadfence();
        float ls = 0.0f, ws = 0.0f;
        for (int i = 0; i < B; i++) {
            ls += __ldcg(&g_loss[i]);
            ws += __ldcg(&g_wsum[i]);
        }
        out[0] = (ls / (float)B) * (ws / ((float)B * (float)L));
    }
}

__global__ __launch_bounds__(128, 1)
void focal_ctc_kernel(const float* __restrict__ lp,      // (T,B,C)
                      const int*   __restrict__ targets, // (B*L)
                      const int*   __restrict__ in_len,  // (B)
                      const int*   __restrict__ tg_len,  // (B)
                      float*       __restrict__ out,
                      int T, int B, int L)
{
    __shared__ float ring[3][RING];   // warp k -> k+1 boundary stream
    __shared__ int   prodCnt[3];      // highest t whose ring value is visible
    __shared__ int   consCnt[4];      // consumer progress (warps 1..3)
    __shared__ float lastv[2];
    __shared__ float sums[CFIX];      // reduce path only
    __shared__ float redw[4];

    const int tid = threadIdx.x, w = tid >> 5, lane = tid & 31;
    const int bid = blockIdx.x;
    const size_t tstr = (size_t)B * CFIX;

    // ================= reduce CTAs: focal weights =================
    if (bid >= B) {
        const int b = bid - B;
        const float* p0 = lp + (size_t)b * CFIX + tid;
        const float* p1 = p0 + 128;
        float acc0 = 0.0f, acc1 = 0.0f;
        int t = 0;
        for (; t + 4 <= T; t += 4) {
            float v0[4], v1[4];
            #pragma unroll
            for (int j = 0; j < 4; j++) {
                v0[j] = __ldcg(p0 + (size_t)(t + j) * tstr);
                v1[j] = __ldcg(p1 + (size_t)(t + j) * tstr);
            }
            #pragma unroll
            for (int j = 0; j < 4; j++) {
                acc0 += ex2f(v0[j] * LOG2E);
                acc1 += ex2f(v1[j] * LOG2E);
            }
        }
        for (; t < T; t++) {
            acc0 += ex2f(__ldcg(p0 + (size_t)t * tstr) * LOG2E);
            acc1 += ex2f(__ldcg(p1 + (size_t)t * tstr) * LOG2E);
        }
        sums[tid] = acc0;
        sums[tid + 128] = acc1;
        __syncthreads();
        float wgt = 0.0f;
        if (tid < L) {
            int   c  = targets[b * L + tid];
            float pr = sums[c] * (1.0f / (float)T);
            float om = 1.0f - pr;
            wgt = om * om;                        // GAMMA = 2
        }
        #pragma unroll
        for (int o = 16; o; o >>= 1) wgt += __shfl_down_sync(0xFFFFFFFFu, wgt, o);
        if (lane == 0) redw[w] = wgt;
        __syncthreads();
        if (tid == 0) {
            g_wsum[b] = redw[0] + redw[1] + redw[2] + redw[3];
            finalize(out, B, L, 2 * B);
        }
        return;
    }

    // ================= scan CTAs =================
    const int b   = bid;
    const int len = in_len[b], tl = tg_len[b];
    const int bL  = b * L;
    const int j   = 32 * w + lane;       // pair index: states u=2j, v=2j+1
    const bool hasU = (j <= L);
    const bool hasV = (j <= L - 1);

    int chV = 0; bool al = false;
    if (hasV) {
        chV = targets[bL + j];
        if (j >= 1) al = (chV != targets[bL + j - 1]);   // chV != 0 always
    }
    const bool capU = (j == tl);         // state 2*tl (aU of pair tl)
    const bool capV = (j == tl - 1);     // state 2*tl-1 (aV of pair tl-1)

    if (tid < 3) prodCnt[tid] = -1;
    if (tid < 4) consCnt[tid] = -1;
    if (tid < 2) lastv[tid] = NEG2;
    __syncthreads();

    const float* rowb = lp + (size_t)b * CFIX;
    const float* pV = rowb + chV;
    const float* pB = rowb;

    // ---- t = 0 ----
    float aU = NEG2, aV = NEG2;
    if (w == 0 && lane == 0) {
        aU = __ldcg(pB) * LOG2E;
        aV = __ldcg(pV) * LOG2E;
    }
    if (lane == 31 && w < 3) {
        ring[w][0] = aV;
        __threadfence_block();
        prodCnt[w] = 0;
    }
    if (len == 1) {
        if (capU) lastv[0] = aU;
        if (capV) lastv[1] = aV;
    }

    // emission prefetch ring (PF steps ahead)
    float eVb[PF], eBb[PF];
    #pragma unroll
    for (int i = 0; i < PF; i++) {
        int tt = 1 + i; if (tt > T - 1) tt = T - 1;
        eVb[i] = __ldcg(pV + (size_t)tt * tstr);
        eBb[i] = __ldcg(pB + (size_t)tt * tstr);
    }

    int availP = 0;      // producer (w-1) progress known to me (lane0, w>0)
    int consAvail = -1;  // consumer (w+1) progress known to me (lane31, w<3)

    for (int t = 1; t < T; t++) {
        const int sl = (t - 1) & (PF - 1);
        // --- neighbor value alpha_{t-1}[2j-1] ---
        float up = __shfl_up_sync(0xFFFFFFFFu, aV, 1);
        float aVm;
        if (lane == 0) {
            if (w == 0) aVm = NEG2;
            else {
                if (availP < t - 1) {
                    do { availP = *(volatile int*)&prodCnt[w - 1]; } while (availP < t - 1);
                    __threadfence_block();   // acquire: ring reads not hoisted
                }
                aVm = ring[w - 1][(t - 1) & (RING - 1)];
            }
        } else aVm = up;

        float eV = eVb[sl], eB = eBb[sl];
        {   // refill slot with row t+PF
            int tn = t + PF; if (tn > T - 1) tn = T - 1;
            eVb[sl] = __ldcg(pV + (size_t)tn * tstr);
            eBb[sl] = __ldcg(pB + (size_t)tn * tstr);
        }

        // --- log2-domain updates (R5 math) ---
        float hiU = fmaxf(aU, aVm), loU = fminf(aU, aVm);
        float nU  = fmaf(eB, LOG2E, hiU + lg2f(1.0f + ex2f(loU - hiU)));
        float a2  = al ? aVm : NEG2;
        float hi  = fmaxf(aV, aU), lo = fminf(aV, aU);
        float m   = fmaxf(hi, a2), o1 = fminf(hi, a2);
        float ss  = 1.0f + ex2f(o1 - m) + ex2f(lo - m);
        float nV  = fmaf(eV, LOG2E, m + lg2f(ss));
        aU = hasU ? nU : NEG2;
        aV = hasV ? nV : NEG2;

        // --- producer: stream boundary value to warp w+1 ---
        if (lane == 31 && w < 3) {
            if (t - consAvail > 40) {      // backpressure (ring is 64 deep)
                do { consAvail = *(volatile int*)&consCnt[w + 1]; } while (t - consAvail > 40);
            }
            ring[w][t & (RING - 1)] = aV;
            if ((t & 15) == 15) { __threadfence_block(); prodCnt[w] = t; }  // release
        }
        // --- consumer progress publish ---
        if (lane == 0 && w > 0 && (t & 15) == 0) consCnt[w] = t;

        if (t == len - 1) {
            if (capU) lastv[0] = aU;
            if (capV) lastv[1] = aV;
        }
    }
    // flush final production so trailing consumers can finish
    if (lane == 31 && w < 3) { __threadfence_block(); prodCnt[w] = T; }
    if (lane == 0 && w > 0)  consCnt[w] = T + RING;   // unblock producers

    __syncthreads();
    if (tid == 0) {
        float la = lastv[0], lb = lastv[1];
        float mm = fmaxf(la, lb);
        float ll = (mm + lg2f(ex2f(la - mm) + ex2f(lb - mm))) * LN2;
        g_loss[b] = (ll > -5e29f) ? -ll : 0.0f;   // zero_infinity
        finalize(out, B, L, 2 * B);
    }
}

extern "C" void kernel_launch(void* const* d_in, const int* in_sizes, int n_in,
                              void* d_out, int out_size)
{
    const float* lp      = (const float*)d_in[0];
    const int*   targets = (const int*)d_in[1];
    const int*   in_len  = (const int*)d_in[2];
    const int*   tg_len  = (const int*)d_in[3];

    int B = in_sizes[2];                 // 64
    int L = in_sizes[1] / B;             // 100
    int T = in_sizes[0] / (B * CFIX);    // 1000

    focal_ctc_kernel<<<2 * B, 128>>>(lp, targets, in_len, tg_len, (float*)d_out, T, B, L);
}

// round 9
// speedup vs baseline: 4.1373x; 4.1373x over previous
#include <cuda_runtime.h>
#include <cstdint>

// Focal CTC loss — paired states + 2 timesteps per barrier.
// grid = 2B. Scan CTAs [0,B): warps 0-3 (threads j=tid<128) hold pair j
//   (states u=2j, v=2j+1); warp 4 owns the cp.async row ring; warps 5-7 exit.
//   Named barrier bar.sync(1,160). Per interval (t, t+1): thread j reads
//   (aU,aV) of pair j-1 and aV of pair j-2 from smem, recomputes aV_t[j-1]
//   redundantly (bitwise identical to thread j-1's own value), so step t+1
//   needs no communication. One float2 STS per interval.
// CTAs [B,2B): coalesced sum_t exp(lp) -> focal weights.
// Final scalar factorizes: mean(outer(w,loss)) = mean(loss)*mean(w).

#define CFIX  256
#define DEPTH 8
#define NEG2  (-1e30f)
#define LOG2E 1.4426950408889634f
#define LN2   0.6931471805599453f

__device__ float g_loss[1024];
__device__ float g_wsum[1024];
__device__ unsigned int g_ctr = 0;

__device__ __forceinline__ float ex2f(float x){ float y; asm("ex2.approx.ftz.f32 %0,%1;":"=f"(y):"f"(x)); return y; }
__device__ __forceinline__ float lg2f(float x){ float y; asm("lg2.approx.ftz.f32 %0,%1;":"=f"(y):"f"(x)); return y; }

__device__ __forceinline__ float lse2e(float a, float b, float e) {
    float hi = fmaxf(a, b), lo = fminf(a, b);
    return fmaf(e, LOG2E, hi + lg2f(1.0f + ex2f(lo - hi)));
}
__device__ __forceinline__ float lse3e(float a, float b, float c, float e) {
    float hi = fmaxf(a, b), lo = fminf(a, b);
    float m  = fmaxf(hi, c), o1 = fminf(hi, c);
    float ss = 1.0f + ex2f(o1 - m) + ex2f(lo - m);
    return fmaf(e, LOG2E, m + lg2f(ss));
}

__device__ __forceinline__ void finalize(float* out, int B, int L, int nCTA)
{
    __threadfence();
    unsigned v = atomicAdd(&g_ctr, 1u);
    if (v == (unsigned)(nCTA - 1)) {
        g_ctr = 0;
        __threadfence();
        float ls = 0.0f, ws = 0.0f;
        for (int i = 0; i < B; i++) {
            ls += __ldcg(&g_loss[i]);
            ws += __ldcg(&g_wsum[i]);
        }
        out[0] = (ls / (float)B) * (ws / ((float)B * (float)L));
    }
}

__global__ __launch_bounds__(256, 1)
void focal_ctc_kernel(const float* __restrict__ lp,      // (T,B,C)
                      const int*   __restrict__ targets, // (B*L)
                      const int*   __restrict__ in_len,  // (B)
                      const int*   __restrict__ tg_len,  // (B)
                      float*       __restrict__ out,
                      int T, int B, int L)
{
    __shared__ __align__(16) float ring[DEPTH][CFIX];  // 8 KB row ring
    __shared__ float2 obuf[2][132];   // pair (aU,aV), 2-pad front, double buffer
    __shared__ float sums[CFIX];      // reduce path
    __shared__ float lastv[2];
    __shared__ float redw[8];

    const int tid = threadIdx.x, w = tid >> 5, lane = tid & 31;
    const int bid = blockIdx.x;
    const size_t tstr = (size_t)B * CFIX;

    // ================= reduce CTAs: focal weights =================
    if (bid >= B) {
        const int b = bid - B;
        const float* p = lp + (size_t)b * CFIX + tid;
        float acc = 0.0f;
        int t = 0;
        for (; t + 8 <= T; t += 8) {
            float v[8];
            #pragma unroll
            for (int j = 0; j < 8; j++) v[j] = __ldcg(p + (size_t)(t + j) * tstr);
            #pragma unroll
            for (int j = 0; j < 8; j++) acc += ex2f(v[j] * LOG2E);
        }
        for (; t < T; t++) acc += ex2f(__ldcg(p + (size_t)t * tstr) * LOG2E);
        sums[tid] = acc;
        __syncthreads();
        float wgt = 0.0f;
        if (tid < L) {
            int   c  = targets[b * L + tid];
            float pr = sums[c] * (1.0f / (float)T);
            float om = 1.0f - pr;
            wgt = om * om;                        // GAMMA = 2
        }
        #pragma unroll
        for (int o = 16; o; o >>= 1) wgt += __shfl_down_sync(0xFFFFFFFFu, wgt, o);
        if (lane == 0) redw[w] = wgt;
        __syncthreads();
        if (tid == 0) {
            float ws = 0.0f;
            #pragma unroll
            for (int i = 0; i < 8; i++) ws += redw[i];
            g_wsum[b] = ws;
            finalize(out, B, L, 2 * B);
        }
        return;
    }

    // ================= scan CTAs =================
    if (w >= 5) return;                  // warps 5-7: gone (named barrier = 160)

    const int b   = bid;
    const int len = in_len[b], tl = tg_len[b];
    const int bL  = b * L;
    const bool cw = (w < 4);
    const int  j  = tid;                 // pair index (compute warps)

    // own pair
    bool hasU = false, hasV = false, al = false;
    int  chV = 0;
    // previous pair (for redundant recompute)
    bool hasVp = false, alp = false;
    int  chVp = 0;
    bool capU = false, capV = false;
    if (cw) {
        hasU = (j <= L);
        hasV = (j <= L - 1);
        if (hasV) {
            chV = targets[bL + j];
            if (j >= 1) al = (chV != targets[bL + j - 1]);
        }
        hasVp = (j >= 1) && (j - 1 <= L - 1);
        if (hasVp) {
            chVp = targets[bL + j - 1];
            if (j >= 2) alp = (chVp != targets[bL + j - 2]);
        }
        capU = (j == tl);
        capV = (j == tl - 1);
    }
    if (tid < 2) {
        obuf[0][tid] = make_float2(NEG2, NEG2);
        obuf[1][tid] = make_float2(NEG2, NEG2);
        lastv[tid] = NEG2;
    }

    const float* rowb = lp + (size_t)b * CFIX;

    // ring prologue (warp 4): rows 0..6 committed, rows 0..2 complete
    if (w == 4) {
        #pragma unroll
        for (int r = 0; r < DEPTH - 1; r++) {
            if (r < T) {
                const float* s0 = rowb + (size_t)r * tstr + lane * 4;
                uint32_t d0 = (uint32_t)__cvta_generic_to_shared(&ring[r][lane * 4]);
                asm volatile("cp.async.ca.shared.global [%0], [%1], 16;" :: "r"(d0), "l"(s0) : "memory");
                asm volatile("cp.async.ca.shared.global [%0], [%1], 16;" :: "r"(d0 + 512), "l"(s0 + 128) : "memory");
            }
            asm volatile("cp.async.commit_group;" ::: "memory");
        }
        asm volatile("cp.async.wait_group 4;" ::: "memory");
    }
    asm volatile("bar.sync 1, 160;" ::: "memory");   // pads + row 0 visible

    // ---- t = 0 ----
    float aU = NEG2, aV = NEG2;
    if (cw) {
        if (j == 0) {
            aU = ring[0][0]   * LOG2E;
            aV = ring[0][chV] * LOG2E;
        }
        obuf[0][2 + j] = make_float2(aU, aV);
        if (len == 1) {
            if (capU) lastv[0] = aU;
            if (capV) lastv[1] = aV;
        }
    }

    int rb = 0;                          // buffer holding alpha_{t-1}
    int t  = 1;
    for (; t + 1 < T; t += 2) {
        asm volatile("bar.sync 1, 160;" ::: "memory");
        if (w == 4) {
            #pragma unroll
            for (int k = 0; k < 2; k++) {
                const int r = t + 6 + k;
                if (r < T) {
                    const float* s0 = rowb + (size_t)r * tstr + lane * 4;
                    uint32_t d0 = (uint32_t)__cvta_generic_to_shared(&ring[r & (DEPTH - 1)][lane * 4]);
                    asm volatile("cp.async.ca.shared.global [%0], [%1], 16;" :: "r"(d0), "l"(s0) : "memory");
                    asm volatile("cp.async.ca.shared.global [%0], [%1], 16;" :: "r"(d0 + 512), "l"(s0 + 128) : "memory");
                }
                asm volatile("cp.async.commit_group;" ::: "memory");
            }
            asm volatile("cp.async.wait_group 4;" ::: "memory");
        } else {
            const float2 pv1 = obuf[rb][1 + j];     // pair j-1 (aU,aV)
            const float  pv2 = obuf[rb][j].y;       // pair j-2 aV
            const float* rt  = &ring[t & (DEPTH - 1)][0];
            const float* rn  = &ring[(t + 1) & (DEPTH - 1)][0];
            float eB0 = rt[0], eV0 = rt[chV], eVp = rt[chVp];
            float eB1 = rn[0], eV1 = rn[chV];
            float aVm1 = pv1.y;
            // --- step t: own pair ---
            float nU = lse2e(aU, aVm1, eB0);
            float nV = lse3e(aV, aU, al ? aVm1 : NEG2, eV0);
            nU = hasU ? nU : NEG2;
            nV = hasV ? nV : NEG2;
            // --- step t: redundant pair j-1 aV (bitwise == neighbor's own) ---
            float nVp = lse3e(pv1.y, pv1.x, alp ? pv2 : NEG2, eVp);
            nVp = hasVp ? nVp : NEG2;
            if (t == len - 1) {
                if (capU) lastv[0] = nU;
                if (capV) lastv[1] = nV;
            }
            // --- step t+1: register-only ---
            float nU2 = lse2e(nU, nVp, eB1);
            float nV2 = lse3e(nV, nU, al ? nVp : NEG2, eV1);
            aU = hasU ? nU2 : NEG2;
            aV = hasV ? nV2 : NEG2;
            obuf[rb ^ 1][2 + j] = make_float2(aU, aV);
            if (t + 1 == len - 1) {
                if (capU) lastv[0] = aU;
                if (capV) lastv[1] = aV;
            }
        }
        rb ^= 1;
    }
    // leftover single step (T even -> t = T-1)
    asm volatile("bar.sync 1, 160;" ::: "memory");
    if (t < T && cw) {
        float aVm1 = obuf[rb][1 + j].y;
        const float* rt = &ring[t & (DEPTH - 1)][0];
        float nU = lse2e(aU, aVm1, rt[0]);
        float nV = lse3e(aV, aU, al ? aVm1 : NEG2, rt[chV]);
        nU = hasU ? nU : NEG2;
        nV = hasV ? nV : NEG2;
        if (t == len - 1) {
            if (capU) lastv[0] = nU;
            if (capV) lastv[1] = nV;
        }
    }
    if (w == 4) { asm volatile("cp.async.wait_group 0;" ::: "memory"); }
    asm volatile("bar.sync 1, 160;" ::: "memory");

    if (tid == 0) {
        float la = lastv[0], lb = lastv[1];
        float m  = fmaxf(la, lb);
        float ll = (m + lg2f(ex2f(la - m) + ex2f(lb - m))) * LN2;
        g_loss[b] = (ll > -5e29f) ? -ll : 0.0f;   // zero_infinity
        finalize(out, B, L, 2 * B);
    }
}

extern "C" void kernel_launch(void* const* d_in, const int* in_sizes, int n_in,
                              void* d_out, int out_size)
{
    const float* lp      = (const float*)d_in[0];
    const int*   targets = (const int*)d_in[1];
    const int*   in_len  = (const int*)d_in[2];
    const int*   tg_len  = (const int*)d_in[3];

    int B = in_sizes[2];                 // 64
    int L = in_sizes[1] / B;             // 100
    int T = in_sizes[0] / (B * CFIX);    // 1000

    focal_ctc_kernel<<<2 * B, 256>>>(lp, targets, in_len, tg_len, (float*)d_out, T, B, L);
}

// round 10
// speedup vs baseline: 6.6299x; 1.6025x over previous
#include <cuda_runtime.h>
#include <cstdint>

// Focal CTC loss — bidirectional scan (alpha forward, beta backward), meeting
// at Tm = len/2: serial chain halves 1000 -> 500 steps.
// grid = 2B. Scan CTAs [0,B), 320 threads:
//   warps 0-3: forward alpha, pair j=tid (states 2j, 2j+1), R9's 2-step
//              redundant interval; warp 8: fwd cp.async ring; barrier 1 (160).
//   warps 4-7: backward beta (mirrored recursion, emissions added per term);
//              warp 9: bwd ring (descending rows); barrier 2 (160).
//   End: __syncthreads, combine ll = LSE_s(alpha_Tm[s] + beta_Tm[s]).
// CTAs [B,2B): coalesced sum_t exp(lp) -> focal weights.
// Final scalar factorizes: mean(outer(w,loss)) = mean(loss)*mean(w).

#define CFIX  256
#define DEPTH 8
#define NEG2  (-1e30f)
#define LOG2E 1.4426950408889634f
#define LN2   0.6931471805599453f

__device__ float g_loss[1024];
__device__ float g_wsum[1024];
__device__ unsigned int g_ctr = 0;

__device__ __forceinline__ float ex2f(float x){ float y; asm("ex2.approx.ftz.f32 %0,%1;":"=f"(y):"f"(x)); return y; }
__device__ __forceinline__ float lg2f(float x){ float y; asm("lg2.approx.ftz.f32 %0,%1;":"=f"(y):"f"(x)); return y; }

// fwd forms: emission factored out (added after LSE)
__device__ __forceinline__ float lse2e(float a, float b, float e) {
    float hi = fmaxf(a, b), lo = fminf(a, b);
    return fmaf(e, LOG2E, hi + lg2f(1.0f + ex2f(lo - hi)));
}
__device__ __forceinline__ float lse3e(float a, float b, float c, float e) {
    float hi = fmaxf(a, b), lo = fminf(a, b);
    float m  = fmaxf(hi, c), o1 = fminf(hi, c);
    return fmaf(e, LOG2E, m + lg2f(1.0f + ex2f(o1 - m) + ex2f(lo - m)));
}
// bwd forms: terms pre-added
__device__ __forceinline__ float lse2(float a, float b) {
    float hi = fmaxf(a, b), lo = fminf(a, b);
    return hi + lg2f(1.0f + ex2f(lo - hi));
}
__device__ __forceinline__ float lse3(float a, float b, float c) {
    float hi = fmaxf(a, b), lo = fminf(a, b);
    float m  = fmaxf(hi, c), o1 = fminf(hi, c);
    return m + lg2f(1.0f + ex2f(o1 - m) + ex2f(lo - m));
}

__device__ __forceinline__ void cpA(uint32_t dst, const float* src){
    asm volatile("cp.async.ca.shared.global [%0], [%1], 16;" :: "r"(dst), "l"(src) : "memory");
}

__device__ __forceinline__ void finalize(float* out, int B, int L, int nCTA)
{
    __threadfence();
    unsigned v = atomicAdd(&g_ctr, 1u);
    if (v == (unsigned)(nCTA - 1)) {
        g_ctr = 0;
        __threadfence();
        float ls = 0.0f, ws = 0.0f;
        for (int i = 0; i < B; i++) {
            ls += __ldcg(&g_loss[i]);
            ws += __ldcg(&g_wsum[i]);
        }
        out[0] = (ls / (float)B) * (ws / ((float)B * (float)L));
    }
}

__global__ __launch_bounds__(320, 1)
void focal_ctc_kernel(const float* __restrict__ lp,      // (T,B,C)
                      const int*   __restrict__ targets, // (B*L)
                      const int*   __restrict__ in_len,  // (B)
                      const int*   __restrict__ tg_len,  // (B)
                      float*       __restrict__ out,
                      int T, int B, int L)
{
    __shared__ __align__(16) float ringF[DEPTH][CFIX];   // 8 KB fwd rows
    __shared__ __align__(16) float ringB[DEPTH][CFIX];   // 8 KB bwd rows
    __shared__ float2 fo[2][132];     // fwd pair (aU,aV), 2-pad FRONT
    __shared__ float2 bo[2][132];     // bwd pair (bU,bV), pads at END (128..131)
    __shared__ float sums[CFIX];      // reduce path
    __shared__ float wmax[4], wsum2[4], redw[10];

    const int tid = threadIdx.x, w = tid >> 5, lane = tid & 31;
    const int bid = blockIdx.x;
    const size_t tstr = (size_t)B * CFIX;

    // ================= reduce CTAs: focal weights =================
    if (bid >= B) {
        const int b = bid - B;
        float acc = 0.0f;
        if (tid < CFIX) {
            const float* p = lp + (size_t)b * CFIX + tid;
            int t = 0;
            for (; t + 8 <= T; t += 8) {
                float v[8];
                #pragma unroll
                for (int k = 0; k < 8; k++) v[k] = __ldcg(p + (size_t)(t + k) * tstr);
                #pragma unroll
                for (int k = 0; k < 8; k++) acc += ex2f(v[k] * LOG2E);
            }
            for (; t < T; t++) acc += ex2f(__ldcg(p + (size_t)t * tstr) * LOG2E);
            sums[tid] = acc;
        }
        __syncthreads();
        float wgt = 0.0f;
        if (tid < L) {
            int   c  = targets[b * L + tid];
            float pr = sums[c] * (1.0f / (float)T);
            float om = 1.0f - pr;
            wgt = om * om;                        // GAMMA = 2
        }
        #pragma unroll
        for (int o = 16; o; o >>= 1) wgt += __shfl_down_sync(0xFFFFFFFFu, wgt, o);
        if (lane == 0) redw[w] = wgt;
        __syncthreads();
        if (tid == 0) {
            float ws = 0.0f;
            #pragma unroll
            for (int i = 0; i < 10; i++) ws += redw[i];
            g_wsum[b] = ws;
            finalize(out, B, L, 2 * B);
        }
        return;
    }

    // ================= scan CTAs =================
    const int b   = bid;
    const int len = in_len[b], tl = tg_len[b];
    const int bL  = b * L;
    const int Tm  = len >> 1;            // meeting point
    const float* rowb = lp + (size_t)b * CFIX;

    // pads
    if (tid < 2) { fo[0][tid] = make_float2(NEG2, NEG2); fo[1][tid] = make_float2(NEG2, NEG2); }
    if (tid >= 128 && tid < 132) {
        bo[0][tid] = make_float2(NEG2, NEG2); bo[1][tid] = make_float2(NEG2, NEG2);
    }

    float aU = NEG2, aV = NEG2;   // final regs used in combine (fwd: alpha, bwd: beta)

    if (w < 4 || w == 8) {
        // ---------------- FORWARD group (barrier 1) ----------------
        const int j = tid;               // only meaningful for w<4
        bool hasU = false, hasV = false, al = false, hasVp = false, alp = false;
        int chV = 0, chVp = 0;
        if (w < 4) {
            hasU = (j <= L); hasV = (j <= L - 1);
            if (hasV) { chV = targets[bL + j]; if (j >= 1) al = (chV != targets[bL + j - 1]); }
            hasVp = (j >= 1) && (j - 1 <= L - 1);
            if (hasVp) { chVp = targets[bL + j - 1]; if (j >= 2) alp = (chVp != targets[bL + j - 2]); }
        }
        if (w == 8) {                    // fwd ring prologue: rows 0..6
            #pragma unroll
            for (int r = 0; r < DEPTH - 1; r++) {
                if (r <= Tm) {
                    const float* s0 = rowb + (size_t)r * tstr + lane * 4;
                    uint32_t d0 = (uint32_t)__cvta_generic_to_shared(&ringF[r & 7][lane * 4]);
                    cpA(d0, s0); cpA(d0 + 512, s0 + 128);
                }
                asm volatile("cp.async.commit_group;" ::: "memory");
            }
            asm volatile("cp.async.wait_group 4;" ::: "memory");
        }
        asm volatile("bar.sync 1, 160;" ::: "memory");

        // t = 0
        if (w < 4) {
            if (j == 0) { aU = ringF[0][0] * LOG2E; aV = ringF[0][chV] * LOG2E; }
            fo[0][2 + j] = make_float2(aU, aV);
        }
        int rb = 0, t = 1;
        for (; t + 1 <= Tm; t += 2) {
            asm volatile("bar.sync 1, 160;" ::: "memory");
            if (w == 8) {
                #pragma unroll
                for (int k = 0; k < 2; k++) {
                    const int r = t + 6 + k;
                    if (r <= Tm) {
                        const float* s0 = rowb + (size_t)r * tstr + lane * 4;
                        uint32_t d0 = (uint32_t)__cvta_generic_to_shared(&ringF[r & 7][lane * 4]);
                        cpA(d0, s0); cpA(d0 + 512, s0 + 128);
                    }
                    asm volatile("cp.async.commit_group;" ::: "memory");
                }
                asm volatile("cp.async.wait_group 4;" ::: "memory");
            } else {
                const float2 pv1 = fo[rb][1 + j];
                const float  pv2 = fo[rb][j].y;
                const float* rt  = &ringF[t & 7][0];
                const float* rn  = &ringF[(t + 1) & 7][0];
                float eB0 = rt[0], eV0 = rt[chV], eVp = rt[chVp];
                float eB1 = rn[0], eV1 = rn[chV];
                float aVm1 = pv1.y;
                float nU = lse2e(aU, aVm1, eB0);
                float nV = lse3e(aV, aU, al ? aVm1 : NEG2, eV0);
                nU = hasU ? nU : NEG2;  nV = hasV ? nV : NEG2;
                float nVp = lse3e(pv1.y, pv1.x, alp ? pv2 : NEG2, eVp);
                nVp = hasVp ? nVp : NEG2;
                float nU2 = lse2e(nU, nVp, eB1);
                float nV2 = lse3e(nV, nU, al ? nVp : NEG2, eV1);
                aU = hasU ? nU2 : NEG2;  aV = hasV ? nV2 : NEG2;
                fo[rb ^ 1][2 + j] = make_float2(aU, aV);
            }
            rb ^= 1;
        }
        if (t <= Tm) {    // leftover single step (Tm odd)
            asm volatile("bar.sync 1, 160;" ::: "memory");
            if (w < 4) {
                float aVm1 = fo[rb][1 + j].y;
                const float* rt = &ringF[t & 7][0];
                float nU = lse2e(aU, aVm1, rt[0]);
                float nV = lse3e(aV, aU, al ? aVm1 : NEG2, rt[chV]);
                aU = hasU ? nU : NEG2;  aV = hasV ? nV : NEG2;
            }
        }
        if (w == 8) { asm volatile("cp.async.wait_group 0;" ::: "memory"); }
    } else {
        // ---------------- BACKWARD group (barrier 2) ----------------
        const int j = tid - 128;         // warps 4-7 compute; warp 9 ring
        const bool bw = (w < 8);         // w in 4..7
        bool hasU = false, hasV = false;
        int ch0 = 0, ch1 = 0, ch2 = 0;   // channels of v_j, v_{j+1}, v_{j+2}
        bool al1 = false, al2 = false;   // skip into v_{j+1}, v_{j+2}
        if (bw) {
            hasU = (j <= L); hasV = (j <= L - 1);
            if (hasV) ch0 = targets[bL + j];
            if (j + 1 <= L - 1) { ch1 = targets[bL + j + 1]; al1 = (ch1 != ch0); }
            if (j + 2 <= L - 1) { ch2 = targets[bL + j + 2]; al2 = (ch2 != ch1); }
        }
        const int nB = len - 1 - Tm;     // number of beta update steps
        if (w == 9) {                    // bwd ring prologue: rows len-1 .. len-7
            #pragma unroll
            for (int i = 0; i < DEPTH - 1; i++) {
                const int r = len - 1 - i;
                if (r >= 0 && i < nB + 1) {
                    const float* s0 = rowb + (size_t)r * tstr + lane * 4;
                    uint32_t d0 = (uint32_t)__cvta_generic_to_shared(&ringB[r & 7][lane * 4]);
                    cpA(d0, s0); cpA(d0 + 512, s0 + 128);
                }
                asm volatile("cp.async.commit_group;" ::: "memory");
            }
            asm volatile("cp.async.wait_group 4;" ::: "memory");
        }
        // init at t = len-1: beta = 0 (log2) at states 2tl (U of pair tl), 2tl-1 (V of pair tl-1)
        if (bw) {
            aU = (j == tl) ? 0.0f : NEG2;        // reuse aU/aV regs as bU/bV
            aV = (j == tl - 1) ? 0.0f : NEG2;
            bo[0][j] = make_float2(aU, aV);
        }
        asm volatile("bar.sync 2, 160;" ::: "memory");

        int rb = 0, k = 0;
        for (; k + 1 < nB; k += 2) {     // steps k (row len-1-k) and k+1 (row len-2-k)
            asm volatile("bar.sync 2, 160;" ::: "memory");
            if (w == 9) {
                #pragma unroll
                for (int q = 0; q < 2; q++) {
                    const int r = len - 1 - (k + 6 + q);
                    if (r >= 0 && (k + 6 + q) < nB + 1) {
                        const float* s0 = rowb + (size_t)r * tstr + lane * 4;
                        uint32_t d0 = (uint32_t)__cvta_generic_to_shared(&ringB[r & 7][lane * 4]);
                        cpA(d0, s0); cpA(d0 + 512, s0 + 128);
                    }
                    asm volatile("cp.async.commit_group;" ::: "memory");
                }
                asm volatile("cp.async.wait_group 4;" ::: "memory");
            } else {
                const float2 n1 = bo[rb][j + 1];
                const float2 n2 = bo[rb][j + 2];
                const int r1 = len - 1 - k, r0 = len - 2 - k;
                const float* R1 = &ringB[r1 & 7][0];
                const float* R0 = &ringB[r0 & 7][0];
                float eB1 = R1[0] * LOG2E, eA1 = R1[ch0] * LOG2E,
                      eC1 = R1[ch1] * LOG2E, eD1 = R1[ch2] * LOG2E;
                float eB0 = R0[0] * LOG2E, eA0 = R0[ch0] * LOG2E,
                      eC0 = R0[ch1] * LOG2E;
                // step k (row r1): own pair
                float nU = lse2(aU + eB1, aV + eA1);
                float nV = lse3(aV + eA1, n1.x + eB1, al1 ? (n1.y + eC1) : NEG2);
                nU = hasU ? nU : NEG2;  nV = hasV ? nV : NEG2;
                // step k: redundant pair j+1 (bitwise == neighbor's own)
                float nU1 = lse2(n1.x + eB1, n1.y + eC1);
                float nV1 = lse3(n1.y + eC1, n2.x + eB1, al2 ? (n2.y + eD1) : NEG2);
                nU1 = (j + 1 <= L) ? nU1 : NEG2;
                nV1 = (j + 1 <= L - 1) ? nV1 : NEG2;
                // step k+1 (row r0): register-only
                float nU2 = lse2(nU + eB0, nV + eA0);
                float nV2 = lse3(nV + eA0, nU1 + eB0, al1 ? (nV1 + eC0) : NEG2);
                aU = hasU ? nU2 : NEG2;  aV = hasV ? nV2 : NEG2;
                bo[rb ^ 1][j] = make_float2(aU, aV);
            }
            rb ^= 1;
        }
        if (k < nB) {                    // leftover single step
            asm volatile("bar.sync 2, 160;" ::: "memory");
            if (bw) {
                const float2 n1 = bo[rb][j + 1];
                const int r1 = len - 1 - k;
                const float* R1 = &ringB[r1 & 7][0];
                float eB1 = R1[0] * LOG2E, eA1 = R1[ch0] * LOG2E, eC1 = R1[ch1] * LOG2E;
                float nU = lse2(aU + eB1, aV + eA1);
                float nV = lse3(aV + eA1, n1.x + eB1, al1 ? (n1.y + eC1) : NEG2);
                aU = hasU ? nU : NEG2;  aV = hasV ? nV : NEG2;
            }
        }
        if (w == 9) { asm volatile("cp.async.wait_group 0;" ::: "memory"); }
        if (bw) bo[0][j] = make_float2(aU, aV);   // publish beta_Tm
    }

    // ---------------- combine: ll = LSE_s(alpha_Tm + beta_Tm) ----------------
    __syncthreads();
    if (w < 4) {
        const int j = tid;
        float2 bb = bo[0][j];
        float cU = aU + bb.x, cV = aV + bb.y;
        float mj = fmaxf(cU, cV);
        #pragma unroll
        for (int o = 16; o; o >>= 1) mj = fmaxf(mj, __shfl_xor_sync(0xFFFFFFFFu, mj, o));
        if (lane == 0) wmax[w] = mj;
    }
    __syncthreads();
    if (w < 4) {
        const int j = tid;
        float M = fmaxf(fmaxf(wmax[0], wmax[1]), fmaxf(wmax[2], wmax[3]));
        float2 bb = bo[0][j];
        float sj = ex2f(aU + bb.x - M) + ex2f(aV + bb.y - M);
        #pragma unroll
        for (int o = 16; o; o >>= 1) sj += __shfl_xor_sync(0xFFFFFFFFu, sj, o);
        if (lane == 0) wsum2[w] = sj;
    }
    __syncthreads();
    if (tid == 0) {
        float M  = fmaxf(fmaxf(wmax[0], wmax[1]), fmaxf(wmax[2], wmax[3]));
        float ss = wsum2[0] + wsum2[1] + wsum2[2] + wsum2[3];
        float ll = (M + lg2f(ss)) * LN2;
        g_loss[b] = (ll > -5e29f) ? -ll : 0.0f;   // zero_infinity
        finalize(out, B, L, 2 * B);
    }
}

extern "C" void kernel_launch(void* const* d_in, const int* in_sizes, int n_in,
                              void* d_out, int out_size)
{
    const float* lp      = (const float*)d_in[0];
    const int*   targets = (const int*)d_in[1];
    const int*   in_len  = (const int*)d_in[2];
    const int*   tg_len  = (const int*)d_in[3];

    int B = in_sizes[2];                 // 64
    int L = in_sizes[1] / B;             // 100
    int T = in_sizes[0] / (B * CFIX);    // 1000

    focal_ctc_kernel<<<2 * B, 320>>>(lp, targets, in_len, tg_len, (float*)d_out, T, B, L);
}